// round 12
// baseline (speedup 1.0000x reference)
#include <cuda_runtime.h>
#include <cuda_bf16.h>
#include <cstdint>

#define B_ 8
#define C_ 128
#define H_ 128
#define W_ 224
#define S_ 81
#define HW_ (H_*W_)

// ---------------- scratch (no allocations allowed) ----------------
__device__ float g_corr[B_*S_*HW_];      // 74.3 MB
__device__ float g_h1  [B_*64*HW_];      // 58.7 MB
__device__ float g_h2  [B_*64*HW_];      // 58.7 MB
__device__ float g_h3  [B_*32*HW_];      // 29.3 MB
// bf16 split weights, layout [shift s][oc][Cpad] (channel-major rows)
__device__ __nv_bfloat16 g_w1h[9*64*256];
__device__ __nv_bfloat16 g_w1l[9*64*256];
__device__ __nv_bfloat16 g_w2h[9*64*64];
__device__ __nv_bfloat16 g_w2l[9*64*64];
__device__ __nv_bfloat16 g_w3h[9*32*64];
__device__ __nv_bfloat16 g_w3l[9*32*64];
__device__ __nv_bfloat16 g_w4h[9*16*64];   // oc padded 2->16
__device__ __nv_bfloat16 g_w4l[9*16*64];

// ---------------- helpers ----------------
__device__ __forceinline__ uint32_t smem_u32(const void* p) {
    uint32_t a;
    asm("{ .reg .u64 t; cvta.to.shared.u64 t, %1; cvt.u32.u64 %0, t; }" : "=r"(a) : "l"(p));
    return a;
}
__device__ __forceinline__ void cpa4(void* smem_dst, const float* gsrc, bool ok) {
    uint32_t d = (uint32_t)__cvta_generic_to_shared(smem_dst);
    asm volatile("cp.async.ca.shared.global [%0], [%1], 4, %2;"
                 :: "r"(d), "l"(gsrc), "r"(ok ? 4 : 0));
}
__device__ __forceinline__ void cpa16(uint32_t smem_dst, const void* gsrc) {
    asm volatile("cp.async.cg.shared.global [%0], [%1], 16;"
                 :: "r"(smem_dst), "l"(gsrc));
}
__device__ __forceinline__ void cpa_commit() { asm volatile("cp.async.commit_group;" ::: "memory"); }
__device__ __forceinline__ void cpa_wait_all() { asm volatile("cp.async.wait_group 0;" ::: "memory"); }
__device__ __forceinline__ void cpa_wait1()   { asm volatile("cp.async.wait_group 1;" ::: "memory"); }

__device__ __forceinline__ uint32_t sw128(uint32_t b) { return b ^ ((b >> 3) & 0x70); }

__device__ __forceinline__ void ldsm4(uint32_t* r, uint32_t addr) {
    asm volatile("ldmatrix.sync.aligned.m8n8.x4.shared.b16 {%0,%1,%2,%3}, [%4];"
                 : "=r"(r[0]), "=r"(r[1]), "=r"(r[2]), "=r"(r[3]) : "r"(addr));
}
__device__ __forceinline__ void mma_bf16(float* c, const uint32_t* a, const uint32_t* b) {
    asm volatile("mma.sync.aligned.m16n8k16.row.col.f32.bf16.bf16.f32 "
                 "{%0,%1,%2,%3}, {%4,%5,%6,%7}, {%8,%9}, {%0,%1,%2,%3};"
                 : "+f"(c[0]), "+f"(c[1]), "+f"(c[2]), "+f"(c[3])
                 : "r"(a[0]), "r"(a[1]), "r"(a[2]), "r"(a[3]), "r"(b[0]), "r"(b[1]));
}
__device__ __forceinline__ uint32_t bf16x2(float hi, float lo) {
    uint32_t r;
    asm("cvt.rn.bf16x2.f32 %0, %1, %2;" : "=r"(r) : "f"(hi), "f"(lo));
    return r;
}

// ------- weight reorder + split: [oc][ci][3][3] -> [s][oc][Cpad], zero-pad c & oc ----
__global__ void k_reorder_split(const float* __restrict__ w, __nv_bfloat16* __restrict__ wh,
                                __nv_bfloat16* __restrict__ wl, int CIN, int COUT, int Cpad,
                                int COUTR) {
    int i = blockIdx.x * 256 + threadIdx.x;
    if (i >= 9 * COUT * Cpad) return;
    int c = i % Cpad;
    int t2 = i / Cpad;
    int oc = t2 % COUT, s = t2 / COUT;
    float v = (c < CIN && oc < COUTR) ? w[(oc * CIN + c) * 9 + s] : 0.0f;
    __nv_bfloat16 h = __float2bfloat16(v);
    wh[i] = h;
    wl[i] = __float2bfloat16(v - __bfloat162float(h));
}

// ---------------- correlation v3: P=2 vertical px/thread, dy-groups of 3 ----------
// Tile 32 cols x 16 rows, 256 thr (32 col x 8 row-threads, each owns rows 2rt,2rt+1).
// For a dy-group {3g..3g+2}, the 2 px x 3 dy window spans 4 halo rows -> 36 LDS.128
// feed 54 shift-uses per 4-ch chunk (1.5x fewer crossbar bytes). Channel-last float4
// halo, conflict-free (lane = col, contiguous 16B). Halo re-staged per group (DRAM
// cheap, cp.async-hidden). acc = 27 shifts x 2 px = 54 regs.
__global__ void __launch_bounds__(256, 2) k_corr(const float* __restrict__ x1,
                                                 const float* __restrict__ x2) {
    __shared__ __align__(16) float4 x2s[2][24][40];   // [buf][halo row][col] . 4 ch
    const int tid = threadIdx.x;
    const int col = tid & 31, rt = tid >> 5;          // rt 0..7
    const int w0 = blockIdx.x * 32, h0 = blockIdx.y * 16, b = blockIdx.z;

    // halo: rows h0-4..h0+19 (24), cols w0-4..w0+35 (40), channels c0..c0+3
    auto load_chunk = [&](int c0, int buf) {
        float* base = (float*)&x2s[buf][0][0];
        for (int idx = tid; idx < 4 * 24 * 40; idx += 256) {
            int c = idx / 960, r2 = idx - c * 960, rr = r2 / 40, cc = r2 - rr * 40;
            int gh = h0 + rr - 4, gw = w0 + cc - 4;
            bool ok = (gh >= 0 && gh < H_ && gw >= 0 && gw < W_);
            const float* src = x2 + ((size_t)(b * C_ + c0 + c) * H_ + (ok ? gh : 0)) * W_ + (ok ? gw : 0);
            cpa4(base + (rr * 40 + cc) * 4 + c, src, ok);
        }
    };

    for (int g = 0; g < 3; g++) {
        __syncthreads();                 // prior group's reads done before restaging
        float acc[27][2];
#pragma unroll
        for (int s = 0; s < 27; s++) { acc[s][0] = 0.f; acc[s][1] = 0.f; }

        load_chunk(0, 0);
        cpa_commit();

        int p = 0;
        for (int c0 = 0; c0 < C_; c0 += 4, p ^= 1) {
            cpa_wait_all();
            __syncthreads();
            if (c0 + 4 < C_) { load_chunk(c0 + 4, p ^ 1); }
            cpa_commit();

            float x1r[2][4];
#pragma unroll
            for (int pp = 0; pp < 2; pp++)
#pragma unroll
                for (int c = 0; c < 4; c++)
                    x1r[pp][c] = x1[((b * C_ + c0 + c) * H_ + h0 + 2 * rt + pp) * W_ + w0 + col];

            const int hrb = 2 * rt + 3 * g;   // halo row base for this thread/group
#pragma unroll
            for (int dx = 0; dx < 9; dx++) {
                float4 v[4];
#pragma unroll
                for (int j = 0; j < 4; j++) v[j] = x2s[p][hrb + j][col + dx];
#pragma unroll
                for (int dyl = 0; dyl < 3; dyl++)
#pragma unroll
                    for (int pp = 0; pp < 2; pp++) {
                        float4 vv = v[dyl + pp];
                        acc[dyl * 9 + dx][pp] += x1r[pp][0] * vv.x + x1r[pp][1] * vv.y
                                               + x1r[pp][2] * vv.z + x1r[pp][3] * vv.w;
                    }
            }
        }
        // write this group's 27 shifts x 2 px
#pragma unroll
        for (int dyl = 0; dyl < 3; dyl++)
#pragma unroll
            for (int dx = 0; dx < 9; dx++) {
                int s = (3 * g + dyl) * 9 + dx;
#pragma unroll
                for (int pp = 0; pp < 2; pp++)
                    g_corr[((size_t)(b * S_ + s) * H_ + h0 + 2 * rt + pp) * W_ + w0 + col] =
                        acc[dyl * 9 + dx][pp] * (1.0f / 128.0f);
            }
    }
}

// ------- shift-decomposed mma.sync conv: 3x3 = 9 shifted 1x1 GEMMs, K = channels ----
// (R9 configuration: 256 threads / 8 warps, 16 px per warp — best measured.)
template<int CIN, int Cpad, int NCHUNK, int COUT, bool SPLIT, bool LEAKY, int NWRITE, int LASTKC>
__global__ void __launch_bounds__(256, 2) k_convmma(const float* __restrict__ in,
                                                    const float* __restrict__ in2,
                                                    const __nv_bfloat16* __restrict__ wh,
                                                    const __nv_bfloat16* __restrict__ wl,
                                                    const float* __restrict__ bias,
                                                    float* __restrict__ out) {
    constexpr int ASZ = 180 * 128;       // halo: 180 px rows x 128B (64ch bf16)
    constexpr int BSZ = COUT * 128;      // B tile: COUT rows x 128B
    constexpr int NT = COUT / 8;
    constexpr int NTP = NT / 2;
    constexpr int T = NCHUNK * 9;

    extern __shared__ __align__(16) char smem_raw[];
    const uint32_t sb = smem_u32(smem_raw);
    const uint32_t Ah = sb, Al = sb + ASZ, Bb = sb + 2 * ASZ;
    const int tid = threadIdx.x, lane = tid & 31, wrp = tid >> 5;
    const int w0 = blockIdx.x * 16, h0 = blockIdx.y * 8, b = blockIdx.z;

    float acc[NT][4];
#pragma unroll
    for (int nt = 0; nt < NT; nt++)
#pragma unroll
        for (int j = 0; j < 4; j++) acc[nt][j] = 0.f;

    const int sub = lane >> 3, r8 = lane & 7;
    const int am = 16 * wrp + r8 + ((sub & 1) << 3);
    const int pr = am >> 4, pc = am & 15;
    const int ak8 = (sub >> 1) << 3;
    const int bn_l = r8 + ((sub >> 1) << 3);
    const int bk8 = (sub & 1) << 3;

    auto stage_halo = [&](int i) {
        constexpr int HITER = (32 * 180 + 255) / 256;   // 23
#pragma unroll
        for (int j = 0; j < HITER; j++) {
            int e = tid + j * 256;
            if (e < 32 * 180) {
                int c2 = e / 180, hp = e - c2 * 180;
                int hr = hp / 18, hc = hp - hr * 18;
                int gh = h0 + hr - 1, gw = w0 + hc - 1;
                bool okp = (gh >= 0 && gh < H_ && gw >= 0 && gw < W_);
                int c0 = i * 64 + c2 * 2;
                float v0 = 0.f, v1 = 0.f;
                if (okp) {
                    if (SPLIT) {
                        if (c0 < 128) {
                            v0 = in[((size_t)(b * 128 + c0    ) * H_ + gh) * W_ + gw];
                            v1 = in[((size_t)(b * 128 + c0 + 1) * H_ + gh) * W_ + gw];
                        } else {
                            if (c0     < 209) v0 = in2[((size_t)(b * 81 + (c0     - 128)) * H_ + gh) * W_ + gw];
                            if (c0 + 1 < 209) v1 = in2[((size_t)(b * 81 + (c0 + 1 - 128)) * H_ + gh) * W_ + gw];
                        }
                    } else {
                        if (c0     < CIN) v0 = in[((size_t)(b * CIN + c0    ) * H_ + gh) * W_ + gw];
                        if (c0 + 1 < CIN) v1 = in[((size_t)(b * CIN + c0 + 1) * H_ + gh) * W_ + gw];
                    }
                }
                uint32_t hpk = bf16x2(v1, v0);
                float l0 = v0 - __uint_as_float(hpk << 16);
                float l1 = v1 - __uint_as_float(hpk & 0xffff0000u);
                uint32_t lpk = bf16x2(l1, l0);
                uint32_t off = (uint32_t)hp * 128 + (((uint32_t)c2 * 4) ^ ((uint32_t)(hp & 7) << 4));
                *(uint32_t*)(smem_raw + off)       = hpk;
                *(uint32_t*)(smem_raw + ASZ + off) = lpk;
            }
        }
    };
    auto stage_B = [&](int t1, int buf) {
        int s = t1 % 9, i = t1 / 9;
#pragma unroll
        for (int j = 0; j < (COUT * 16 + 255) / 256; j++) {
            int q = tid + j * 256;
            if (q < COUT * 16) {
                int split = q / (COUT * 8);
                int r = q - split * (COUT * 8);
                int oc = r >> 3, seg = r & 7;
                const __nv_bfloat16* src =
                    (split ? wl : wh) + (size_t)(s * COUT + oc) * Cpad + i * 64 + seg * 8;
                cpa16(Bb + (uint32_t)(buf * 2 + split) * BSZ + sw128((uint32_t)(oc * 128 + seg * 16)), src);
            }
        }
        cpa_commit();
    };

    stage_B(0, 0);
    if (T > 1) stage_B(1, 1);
    int t = 0;
    for (int i = 0; i < NCHUNK; i++) {
        __syncthreads();
        stage_halo(i);
        const int kcmax = (i == NCHUNK - 1) ? LASTKC : 4;
#pragma unroll 1
        for (int s = 0; s < 9; s++) {
            if (t + 1 < T) cpa_wait1(); else cpa_wait_all();
            __syncthreads();
            if (t + 2 < T) stage_B(t + 2, (t + 2) % 3);
            const int buf = t % 3;

            const int ky = s / 3, kx = s - ky * 3;
            const int hr = (pr + ky) * 18 + (pc + kx);
            const uint32_t arow = (uint32_t)hr * 128;
            const uint32_t axor = (uint32_t)(hr & 7) << 4;
            const uint32_t Bhc = Bb + (uint32_t)(buf * 2 + 0) * BSZ;
            const uint32_t Blc = Bb + (uint32_t)(buf * 2 + 1) * BSZ;
#pragma unroll
            for (int kc = 0; kc < 4; kc++) {
                if (kc < kcmax) {
                    uint32_t ka = ((uint32_t)((kc * 16 + ak8) * 2)) ^ axor;
                    uint32_t ahf[4], alf[4];
                    ldsm4(ahf, Ah + arow + ka);
                    ldsm4(alf, Al + arow + ka);
                    uint32_t bhf[NTP][4], blf[NTP][4];
#pragma unroll
                    for (int tp = 0; tp < NTP; tp++) {
                        int bn = tp * 16 + bn_l;
                        uint32_t boff = (uint32_t)bn * 128
                                      + (((uint32_t)((kc * 16 + bk8) * 2)) ^ ((uint32_t)(bn & 7) << 4));
                        ldsm4(bhf[tp], Bhc + boff);
                        ldsm4(blf[tp], Blc + boff);
                    }
#pragma unroll
                    for (int tp = 0; tp < NTP; tp++) {
                        mma_bf16(acc[2 * tp],     ahf, bhf[tp]);
                        mma_bf16(acc[2 * tp + 1], ahf, bhf[tp] + 2);
                    }
#pragma unroll
                    for (int tp = 0; tp < NTP; tp++) {
                        mma_bf16(acc[2 * tp],     ahf, blf[tp]);
                        mma_bf16(acc[2 * tp + 1], ahf, blf[tp] + 2);
                    }
#pragma unroll
                    for (int tp = 0; tp < NTP; tp++) {
                        mma_bf16(acc[2 * tp],     alf, bhf[tp]);
                        mma_bf16(acc[2 * tp + 1], alf, bhf[tp] + 2);
                    }
                }
            }
            t++;
        }
    }

    const int m1 = 16 * wrp + lane / 4, m2 = m1 + 8;
    const int cb = (lane % 4) * 2;
    const int gh1 = h0 + (m1 >> 4), gw1 = w0 + (m1 & 15);
    const int gh2 = h0 + (m2 >> 4), gw2 = w0 + (m2 & 15);
#pragma unroll
    for (int nt = 0; nt < NT; nt++) {
        int n0 = nt * 8 + cb;
        if (n0 < NWRITE) {
            float b0v = bias[n0], b1v = bias[n0 + 1];
            float v00 = acc[nt][0] + b0v, v01 = acc[nt][1] + b1v;
            float v10 = acc[nt][2] + b0v, v11 = acc[nt][3] + b1v;
            if (LEAKY) {
                v00 = fmaxf(v00, 0.1f * v00); v01 = fmaxf(v01, 0.1f * v01);
                v10 = fmaxf(v10, 0.1f * v10); v11 = fmaxf(v11, 0.1f * v11);
            }
            out[((size_t)(b * NWRITE + n0    ) * H_ + gh1) * W_ + gw1] = v00;
            out[((size_t)(b * NWRITE + n0 + 1) * H_ + gh1) * W_ + gw1] = v01;
            out[((size_t)(b * NWRITE + n0    ) * H_ + gh2) * W_ + gw2] = v10;
            out[((size_t)(b * NWRITE + n0 + 1) * H_ + gh2) * W_ + gw2] = v11;
        }
    }
}

// ---------------- launch ----------------
extern "C" void kernel_launch(void* const* d_in, const int* in_sizes, int n_in,
                              void* d_out, int out_size) {
    (void)in_sizes; (void)n_in; (void)out_size;
    const float* x1 = (const float*)d_in[0];
    const float* x2 = (const float*)d_in[1];
    const float* w1 = (const float*)d_in[2];
    const float* b1 = (const float*)d_in[3];
    const float* w2 = (const float*)d_in[4];
    const float* b2 = (const float*)d_in[5];
    const float* w3 = (const float*)d_in[6];
    const float* b3 = (const float*)d_in[7];
    const float* w4 = (const float*)d_in[8];
    const float* b4 = (const float*)d_in[9];
    float* out = (float*)d_out;

    float *corr, *h1, *h2, *h3;
    __nv_bfloat16 *w1h, *w1l, *w2h, *w2l, *w3h, *w3l, *w4h, *w4l;
    cudaGetSymbolAddress((void**)&corr, g_corr);
    cudaGetSymbolAddress((void**)&h1,   g_h1);
    cudaGetSymbolAddress((void**)&h2,   g_h2);
    cudaGetSymbolAddress((void**)&h3,   g_h3);
    cudaGetSymbolAddress((void**)&w1h,  g_w1h);
    cudaGetSymbolAddress((void**)&w1l,  g_w1l);
    cudaGetSymbolAddress((void**)&w2h,  g_w2h);
    cudaGetSymbolAddress((void**)&w2l,  g_w2l);
    cudaGetSymbolAddress((void**)&w3h,  g_w3h);
    cudaGetSymbolAddress((void**)&w3l,  g_w3l);
    cudaGetSymbolAddress((void**)&w4h,  g_w4h);
    cudaGetSymbolAddress((void**)&w4l,  g_w4l);

    // smem: hi/lo halo (2 x 23040) + B triple buffer (3 x 2 x BSZ)
    constexpr int SM64 = 2 * 180 * 128 + 6 * 64 * 128;   // 95232
    constexpr int SM32 = 2 * 180 * 128 + 6 * 32 * 128;   // 70656
    constexpr int SM16 = 2 * 180 * 128 + 6 * 16 * 128;   // 58368
    static bool attr_done = false;
    if (!attr_done) {
        cudaFuncSetAttribute(k_convmma<209, 256, 4, 64, true , true , 64, 2>, cudaFuncAttributeMaxDynamicSharedMemorySize, SM64);
        cudaFuncSetAttribute(k_convmma< 64,  64, 1, 64, false, true , 64, 4>, cudaFuncAttributeMaxDynamicSharedMemorySize, SM64);
        cudaFuncSetAttribute(k_convmma< 64,  64, 1, 32, false, true , 32, 4>, cudaFuncAttributeMaxDynamicSharedMemorySize, SM32);
        cudaFuncSetAttribute(k_convmma< 32,  64, 1, 16, false, false,  2, 2>, cudaFuncAttributeMaxDynamicSharedMemorySize, SM16);
        attr_done = true;
    }

    k_reorder_split<<<(9 * 64 * 256 + 255) / 256, 256>>>(w1, w1h, w1l, 209, 64, 256, 64);
    k_reorder_split<<<(9 * 64 * 64  + 255) / 256, 256>>>(w2, w2h, w2l,  64, 64,  64, 64);
    k_reorder_split<<<(9 * 32 * 64  + 255) / 256, 256>>>(w3, w3h, w3l,  64, 32,  64, 32);
    k_reorder_split<<<(9 * 16 * 64  + 255) / 256, 256>>>(w4, w4h, w4l,  32, 16,  64,  2);

    dim3 gridC(W_ / 32, H_ / 16, B_);  // (7, 8, 8)   corr v3 (32x16 tiles)
    dim3 gridT(W_ / 16, H_ / 8, B_);   // (14, 16, 8) mma convs

    k_corr<<<gridC, 256>>>(x1, x2);
    k_convmma<209, 256, 4, 64, true , true , 64, 2><<<gridT, 256, SM64>>>(x1, corr, w1h, w1l, b1, h1);
    k_convmma< 64,  64, 1, 64, false, true , 64, 4><<<gridT, 256, SM64>>>(h1, nullptr, w2h, w2l, b2, h2);
    k_convmma< 64,  64, 1, 32, false, true , 32, 4><<<gridT, 256, SM32>>>(h2, nullptr, w3h, w3l, b3, h3);
    k_convmma< 32,  64, 1, 16, false, false,  2, 2><<<gridT, 256, SM16>>>(h3, nullptr, w4h, w4l, b4, out);
}

// round 13
// speedup vs baseline: 1.0677x; 1.0677x over previous
#include <cuda_runtime.h>
#include <cuda_bf16.h>
#include <cstdint>

#define B_ 8
#define C_ 128
#define H_ 128
#define W_ 224
#define S_ 81
#define HW_ (H_*W_)

// ---------------- scratch (no allocations allowed) ----------------
__device__ float g_corr[B_*S_*HW_];      // 74.3 MB
__device__ float g_h1  [B_*64*HW_];      // 58.7 MB
__device__ float g_h2  [B_*64*HW_];      // 58.7 MB
__device__ float g_h3  [B_*32*HW_];      // 29.3 MB
// bf16 split weights, layout [shift s][oc][Cpad] (channel-major rows)
__device__ __nv_bfloat16 g_w1h[9*64*256];
__device__ __nv_bfloat16 g_w1l[9*64*256];
__device__ __nv_bfloat16 g_w2h[9*64*64];
__device__ __nv_bfloat16 g_w2l[9*64*64];
__device__ __nv_bfloat16 g_w3h[9*32*64];
__device__ __nv_bfloat16 g_w3l[9*32*64];
__device__ __nv_bfloat16 g_w4h[9*16*64];   // oc padded 2->16
__device__ __nv_bfloat16 g_w4l[9*16*64];

// ---------------- helpers ----------------
__device__ __forceinline__ uint32_t smem_u32(const void* p) {
    uint32_t a;
    asm("{ .reg .u64 t; cvta.to.shared.u64 t, %1; cvt.u32.u64 %0, t; }" : "=r"(a) : "l"(p));
    return a;
}
__device__ __forceinline__ void cpa4(void* smem_dst, const float* gsrc, bool ok) {
    uint32_t d = (uint32_t)__cvta_generic_to_shared(smem_dst);
    asm volatile("cp.async.ca.shared.global [%0], [%1], 4, %2;"
                 :: "r"(d), "l"(gsrc), "r"(ok ? 4 : 0));
}
__device__ __forceinline__ void cpa16(uint32_t smem_dst, const void* gsrc) {
    asm volatile("cp.async.cg.shared.global [%0], [%1], 16;"
                 :: "r"(smem_dst), "l"(gsrc));
}
__device__ __forceinline__ void cpa_commit() { asm volatile("cp.async.commit_group;" ::: "memory"); }
__device__ __forceinline__ void cpa_wait_all() { asm volatile("cp.async.wait_group 0;" ::: "memory"); }
__device__ __forceinline__ void cpa_wait1()   { asm volatile("cp.async.wait_group 1;" ::: "memory"); }

__device__ __forceinline__ uint32_t sw128(uint32_t b) { return b ^ ((b >> 3) & 0x70); }

__device__ __forceinline__ void ldsm4(uint32_t* r, uint32_t addr) {
    asm volatile("ldmatrix.sync.aligned.m8n8.x4.shared.b16 {%0,%1,%2,%3}, [%4];"
                 : "=r"(r[0]), "=r"(r[1]), "=r"(r[2]), "=r"(r[3]) : "r"(addr));
}
__device__ __forceinline__ void mma_bf16(float* c, const uint32_t* a, const uint32_t* b) {
    asm volatile("mma.sync.aligned.m16n8k16.row.col.f32.bf16.bf16.f32 "
                 "{%0,%1,%2,%3}, {%4,%5,%6,%7}, {%8,%9}, {%0,%1,%2,%3};"
                 : "+f"(c[0]), "+f"(c[1]), "+f"(c[2]), "+f"(c[3])
                 : "r"(a[0]), "r"(a[1]), "r"(a[2]), "r"(a[3]), "r"(b[0]), "r"(b[1]));
}
__device__ __forceinline__ uint32_t bf16x2(float hi, float lo) {
    uint32_t r;
    asm("cvt.rn.bf16x2.f32 %0, %1, %2;" : "=r"(r) : "f"(hi), "f"(lo));
    return r;
}

// ------- weight reorder + split: [oc][ci][3][3] -> [s][oc][Cpad], zero-pad c & oc ----
__global__ void k_reorder_split(const float* __restrict__ w, __nv_bfloat16* __restrict__ wh,
                                __nv_bfloat16* __restrict__ wl, int CIN, int COUT, int Cpad,
                                int COUTR) {
    int i = blockIdx.x * 256 + threadIdx.x;
    if (i >= 9 * COUT * Cpad) return;
    int c = i % Cpad;
    int t2 = i / Cpad;
    int oc = t2 % COUT, s = t2 / COUT;
    float v = (c < CIN && oc < COUTR) ? w[(oc * CIN + c) * 9 + s] : 0.0f;
    __nv_bfloat16 h = __float2bfloat16(v);
    wh[i] = h;
    wl[i] = __float2bfloat16(v - __bfloat162float(h));
}

// ---------------- correlation (R9 scalar version — proven 361us) ----------
__global__ void __launch_bounds__(256, 2) k_corr(const float* __restrict__ x1,
                                                 const float* __restrict__ x2) {
    __shared__ __align__(16) float x2s[2][4][16][40];
    const int tid = threadIdx.x;
    const int col = tid & 31, row = tid >> 5;
    const int w0 = blockIdx.x * 32, h0 = blockIdx.y * 8, b = blockIdx.z;

    float acc[81];
#pragma unroll
    for (int s = 0; s < 81; s++) acc[s] = 0.f;

    auto load_chunk = [&](int c0, int buf) {
        float* base = &x2s[buf][0][0][0];
        for (int idx = tid; idx < 4 * 16 * 40; idx += 256) {
            int c = idx / 640, r2 = idx % 640, rr = r2 / 40, cc = r2 % 40;
            int gh = h0 + rr - 4, gw = w0 + cc - 4;
            bool ok = (gh >= 0 && gh < H_ && gw >= 0 && gw < W_);
            const float* src = x2 + ((size_t)(b * C_ + c0 + c) * H_ + (ok ? gh : 0)) * W_ + (ok ? gw : 0);
            cpa4(base + idx, src, ok);
        }
    };

    load_chunk(0, 0);
    cpa_commit();

    int p = 0;
    for (int c0 = 0; c0 < C_; c0 += 4, p ^= 1) {
        cpa_wait_all();
        __syncthreads();
        if (c0 + 4 < C_) load_chunk(c0 + 4, p ^ 1);
        cpa_commit();

        float x1r[4];
#pragma unroll
        for (int c = 0; c < 4; c++)
            x1r[c] = x1[((b * C_ + c0 + c) * H_ + h0 + row) * W_ + w0 + col];
#pragma unroll
        for (int c = 0; c < 4; c++) {
            float v = x1r[c];
#pragma unroll
            for (int dy = 0; dy < 9; dy++)
#pragma unroll
                for (int dx = 0; dx < 9; dx++)
                    acc[dy * 9 + dx] += v * x2s[p][c][row + dy][col + dx];
        }
    }
#pragma unroll
    for (int s = 0; s < 81; s++)
        g_corr[((b * S_ + s) * H_ + h0 + row) * W_ + w0 + col] = acc[s] * (1.0f / 128.0f);
}

// ------- shift-decomposed mma.sync conv: 3x3 = 9 shifted 1x1 GEMMs, K = channels ----
// R9 config (256 thr / 8 warps). CHOFF: global channel offset (for split conv1).
// ACCIN: initialize accumulators from `out` (partial-sum continuation).
// RAWOUT: write raw acc (no bias/leaky) for later continuation.
template<int CIN, int Cpad, int NCHUNK, int COUT, bool SPLIT, bool LEAKY, int NWRITE,
         int LASTKC, int CHOFF, bool ACCIN, bool RAWOUT>
__global__ void __launch_bounds__(256, 2) k_convmma(const float* __restrict__ in,
                                                    const float* __restrict__ in2,
                                                    const __nv_bfloat16* __restrict__ wh,
                                                    const __nv_bfloat16* __restrict__ wl,
                                                    const float* __restrict__ bias,
                                                    float* __restrict__ out) {
    constexpr int ASZ = 180 * 128;       // halo: 180 px rows x 128B (64ch bf16)
    constexpr int BSZ = COUT * 128;      // B tile: COUT rows x 128B
    constexpr int NT = COUT / 8;
    constexpr int NTP = NT / 2;
    constexpr int T = NCHUNK * 9;

    extern __shared__ __align__(16) char smem_raw[];
    const uint32_t sb = smem_u32(smem_raw);
    const uint32_t Ah = sb, Al = sb + ASZ, Bb = sb + 2 * ASZ;
    const int tid = threadIdx.x, lane = tid & 31, wrp = tid >> 5;
    const int w0 = blockIdx.x * 16, h0 = blockIdx.y * 8, b = blockIdx.z;

    const int sub = lane >> 3, r8 = lane & 7;
    const int am = 16 * wrp + r8 + ((sub & 1) << 3);
    const int pr = am >> 4, pc = am & 15;
    const int ak8 = (sub >> 1) << 3;
    const int bn_l = r8 + ((sub >> 1) << 3);
    const int bk8 = (sub & 1) << 3;

    // epilogue/acc-in addressing
    const int m1 = 16 * wrp + lane / 4, m2 = m1 + 8;
    const int cb = (lane % 4) * 2;
    const int gh1 = h0 + (m1 >> 4), gw1 = w0 + (m1 & 15);
    const int gh2 = h0 + (m2 >> 4), gw2 = w0 + (m2 & 15);

    float acc[NT][4];
    if (ACCIN) {
#pragma unroll
        for (int nt = 0; nt < NT; nt++) {
            int n0 = nt * 8 + cb;
            acc[nt][0] = out[((size_t)(b * NWRITE + n0    ) * H_ + gh1) * W_ + gw1];
            acc[nt][1] = out[((size_t)(b * NWRITE + n0 + 1) * H_ + gh1) * W_ + gw1];
            acc[nt][2] = out[((size_t)(b * NWRITE + n0    ) * H_ + gh2) * W_ + gw2];
            acc[nt][3] = out[((size_t)(b * NWRITE + n0 + 1) * H_ + gh2) * W_ + gw2];
        }
    } else {
#pragma unroll
        for (int nt = 0; nt < NT; nt++)
#pragma unroll
            for (int j = 0; j < 4; j++) acc[nt][j] = 0.f;
    }

    auto stage_halo = [&](int i) {
        constexpr int HITER = (32 * 180 + 255) / 256;   // 23
#pragma unroll
        for (int j = 0; j < HITER; j++) {
            int e = tid + j * 256;
            if (e < 32 * 180) {
                int c2 = e / 180, hp = e - c2 * 180;
                int hr = hp / 18, hc = hp - hr * 18;
                int gh = h0 + hr - 1, gw = w0 + hc - 1;
                bool okp = (gh >= 0 && gh < H_ && gw >= 0 && gw < W_);
                int c0 = CHOFF + i * 64 + c2 * 2;
                float v0 = 0.f, v1 = 0.f;
                if (okp) {
                    if (SPLIT) {
                        if (c0 < 128) {
                            v0 = in[((size_t)(b * 128 + c0    ) * H_ + gh) * W_ + gw];
                            v1 = in[((size_t)(b * 128 + c0 + 1) * H_ + gh) * W_ + gw];
                        } else {
                            if (c0     < 209) v0 = in2[((size_t)(b * 81 + (c0     - 128)) * H_ + gh) * W_ + gw];
                            if (c0 + 1 < 209) v1 = in2[((size_t)(b * 81 + (c0 + 1 - 128)) * H_ + gh) * W_ + gw];
                        }
                    } else {
                        if (c0     < CIN) v0 = in[((size_t)(b * CIN + c0    ) * H_ + gh) * W_ + gw];
                        if (c0 + 1 < CIN) v1 = in[((size_t)(b * CIN + c0 + 1) * H_ + gh) * W_ + gw];
                    }
                }
                uint32_t hpk = bf16x2(v1, v0);
                float l0 = v0 - __uint_as_float(hpk << 16);
                float l1 = v1 - __uint_as_float(hpk & 0xffff0000u);
                uint32_t lpk = bf16x2(l1, l0);
                uint32_t off = (uint32_t)hp * 128 + (((uint32_t)c2 * 4) ^ ((uint32_t)(hp & 7) << 4));
                *(uint32_t*)(smem_raw + off)       = hpk;
                *(uint32_t*)(smem_raw + ASZ + off) = lpk;
            }
        }
    };
    auto stage_B = [&](int t1, int buf) {
        int s = t1 % 9, ig = CHOFF / 64 + t1 / 9;
#pragma unroll
        for (int j = 0; j < (COUT * 16 + 255) / 256; j++) {
            int q = tid + j * 256;
            if (q < COUT * 16) {
                int split = q / (COUT * 8);
                int r = q - split * (COUT * 8);
                int oc = r >> 3, seg = r & 7;
                const __nv_bfloat16* src =
                    (split ? wl : wh) + (size_t)(s * COUT + oc) * Cpad + ig * 64 + seg * 8;
                cpa16(Bb + (uint32_t)(buf * 2 + split) * BSZ + sw128((uint32_t)(oc * 128 + seg * 16)), src);
            }
        }
        cpa_commit();
    };

    stage_B(0, 0);
    if (T > 1) stage_B(1, 1);
    int t = 0;
    for (int i = 0; i < NCHUNK; i++) {
        __syncthreads();
        stage_halo(i);
        const int kcmax = (i == NCHUNK - 1) ? LASTKC : 4;
#pragma unroll 1
        for (int s = 0; s < 9; s++) {
            if (t + 1 < T) cpa_wait1(); else cpa_wait_all();
            __syncthreads();
            if (t + 2 < T) stage_B(t + 2, (t + 2) % 3);
            const int buf = t % 3;

            const int ky = s / 3, kx = s - ky * 3;
            const int hr = (pr + ky) * 18 + (pc + kx);
            const uint32_t arow = (uint32_t)hr * 128;
            const uint32_t axor = (uint32_t)(hr & 7) << 4;
            const uint32_t Bhc = Bb + (uint32_t)(buf * 2 + 0) * BSZ;
            const uint32_t Blc = Bb + (uint32_t)(buf * 2 + 1) * BSZ;
#pragma unroll
            for (int kc = 0; kc < 4; kc++) {
                if (kc < kcmax) {
                    uint32_t ka = ((uint32_t)((kc * 16 + ak8) * 2)) ^ axor;
                    uint32_t ahf[4], alf[4];
                    ldsm4(ahf, Ah + arow + ka);
                    ldsm4(alf, Al + arow + ka);
                    uint32_t bhf[NTP][4], blf[NTP][4];
#pragma unroll
                    for (int tp = 0; tp < NTP; tp++) {
                        int bn = tp * 16 + bn_l;
                        uint32_t boff = (uint32_t)bn * 128
                                      + (((uint32_t)((kc * 16 + bk8) * 2)) ^ ((uint32_t)(bn & 7) << 4));
                        ldsm4(bhf[tp], Bhc + boff);
                        ldsm4(blf[tp], Blc + boff);
                    }
#pragma unroll
                    for (int tp = 0; tp < NTP; tp++) {
                        mma_bf16(acc[2 * tp],     ahf, bhf[tp]);
                        mma_bf16(acc[2 * tp + 1], ahf, bhf[tp] + 2);
                    }
#pragma unroll
                    for (int tp = 0; tp < NTP; tp++) {
                        mma_bf16(acc[2 * tp],     ahf, blf[tp]);
                        mma_bf16(acc[2 * tp + 1], ahf, blf[tp] + 2);
                    }
#pragma unroll
                    for (int tp = 0; tp < NTP; tp++) {
                        mma_bf16(acc[2 * tp],     alf, bhf[tp]);
                        mma_bf16(acc[2 * tp + 1], alf, bhf[tp] + 2);
                    }
                }
            }
            t++;
        }
    }

#pragma unroll
    for (int nt = 0; nt < NT; nt++) {
        int n0 = nt * 8 + cb;
        if (n0 < NWRITE) {
            float v00 = acc[nt][0], v01 = acc[nt][1], v10 = acc[nt][2], v11 = acc[nt][3];
            if (!RAWOUT) {
                float b0v = bias[n0], b1v = bias[n0 + 1];
                v00 += b0v; v01 += b1v; v10 += b0v; v11 += b1v;
                if (LEAKY) {
                    v00 = fmaxf(v00, 0.1f * v00); v01 = fmaxf(v01, 0.1f * v01);
                    v10 = fmaxf(v10, 0.1f * v10); v11 = fmaxf(v11, 0.1f * v11);
                }
            }
            out[((size_t)(b * NWRITE + n0    ) * H_ + gh1) * W_ + gw1] = v00;
            out[((size_t)(b * NWRITE + n0 + 1) * H_ + gh1) * W_ + gw1] = v01;
            out[((size_t)(b * NWRITE + n0    ) * H_ + gh2) * W_ + gw2] = v10;
            out[((size_t)(b * NWRITE + n0 + 1) * H_ + gh2) * W_ + gw2] = v11;
        }
    }
}

// ---------------- launch: fork corr onto a side stream, overlap with conv1a -------
extern "C" void kernel_launch(void* const* d_in, const int* in_sizes, int n_in,
                              void* d_out, int out_size) {
    (void)in_sizes; (void)n_in; (void)out_size;
    const float* x1 = (const float*)d_in[0];
    const float* x2 = (const float*)d_in[1];
    const float* w1 = (const float*)d_in[2];
    const float* b1 = (const float*)d_in[3];
    const float* w2 = (const float*)d_in[4];
    const float* b2 = (const float*)d_in[5];
    const float* w3 = (const float*)d_in[6];
    const float* b3 = (const float*)d_in[7];
    const float* w4 = (const float*)d_in[8];
    const float* b4 = (const float*)d_in[9];
    float* out = (float*)d_out;

    float *corr, *h1, *h2, *h3;
    __nv_bfloat16 *w1h, *w1l, *w2h, *w2l, *w3h, *w3l, *w4h, *w4l;
    cudaGetSymbolAddress((void**)&corr, g_corr);
    cudaGetSymbolAddress((void**)&h1,   g_h1);
    cudaGetSymbolAddress((void**)&h2,   g_h2);
    cudaGetSymbolAddress((void**)&h3,   g_h3);
    cudaGetSymbolAddress((void**)&w1h,  g_w1h);
    cudaGetSymbolAddress((void**)&w1l,  g_w1l);
    cudaGetSymbolAddress((void**)&w2h,  g_w2h);
    cudaGetSymbolAddress((void**)&w2l,  g_w2l);
    cudaGetSymbolAddress((void**)&w3h,  g_w3h);
    cudaGetSymbolAddress((void**)&w3l,  g_w3l);
    cudaGetSymbolAddress((void**)&w4h,  g_w4h);
    cudaGetSymbolAddress((void**)&w4l,  g_w4l);

    constexpr int SM64 = 2 * 180 * 128 + 6 * 64 * 128;   // 95232
    constexpr int SM32 = 2 * 180 * 128 + 6 * 32 * 128;   // 70656
    constexpr int SM16 = 2 * 180 * 128 + 6 * 16 * 128;   // 58368

    static cudaStream_t s2;
    static cudaEvent_t evFork, evJoin;
    static bool init_done = false;
    if (!init_done) {
        // First call is the uncaptured correctness run: safe to create resources here.
        cudaStreamCreateWithFlags(&s2, cudaStreamNonBlocking);
        cudaEventCreateWithFlags(&evFork, cudaEventDisableTiming);
        cudaEventCreateWithFlags(&evJoin, cudaEventDisableTiming);
        cudaFuncSetAttribute(k_convmma<128, 256, 2, 64, false, false, 64, 4,   0, false, true >, cudaFuncAttributeMaxDynamicSharedMemorySize, SM64);
        cudaFuncSetAttribute(k_convmma<209, 256, 2, 64, true , true , 64, 2, 128, true , false>, cudaFuncAttributeMaxDynamicSharedMemorySize, SM64);
        cudaFuncSetAttribute(k_convmma< 64,  64, 1, 64, false, true , 64, 4,   0, false, false>, cudaFuncAttributeMaxDynamicSharedMemorySize, SM64);
        cudaFuncSetAttribute(k_convmma< 64,  64, 1, 32, false, true , 32, 4,   0, false, false>, cudaFuncAttributeMaxDynamicSharedMemorySize, SM32);
        cudaFuncSetAttribute(k_convmma< 32,  64, 1, 16, false, false,  2, 2,   0, false, false>, cudaFuncAttributeMaxDynamicSharedMemorySize, SM16);
        init_done = true;
    }

    dim3 gridC(W_ / 32, H_ / 8, B_);   // (7, 16, 8)  corr
    dim3 gridT(W_ / 16, H_ / 8, B_);   // (14, 16, 8) mma convs

    // Fork: corr on s2, concurrent with reorders + conv1a on the main stream.
    cudaEventRecord(evFork, 0);
    cudaStreamWaitEvent(s2, evFork, 0);
    k_corr<<<gridC, 256, 0, s2>>>(x1, x2);
    cudaEventRecord(evJoin, s2);

    k_reorder_split<<<(9 * 64 * 256 + 255) / 256, 256>>>(w1, w1h, w1l, 209, 64, 256, 64);
    k_reorder_split<<<(9 * 64 * 64  + 255) / 256, 256>>>(w2, w2h, w2l,  64, 64,  64, 64);
    k_reorder_split<<<(9 * 32 * 64  + 255) / 256, 256>>>(w3, w3h, w3l,  64, 32,  64, 32);
    k_reorder_split<<<(9 * 16 * 64  + 255) / 256, 256>>>(w4, w4h, w4l,  32, 16,  64,  2);

    // conv1a: x1 channels 0..127 -> raw partial sums into h1 (no bias/leaky)
    k_convmma<128, 256, 2, 64, false, false, 64, 4,   0, false, true ><<<gridT, 256, SM64>>>(x1, nullptr, w1h, w1l, b1, h1);

    // Join: conv1b needs corr.
    cudaStreamWaitEvent(0, evJoin, 0);

    // conv1b: corr channels 128..208, acc-in from h1, bias + leaky
    k_convmma<209, 256, 2, 64, true , true , 64, 2, 128, true , false><<<gridT, 256, SM64>>>(x1, corr, w1h, w1l, b1, h1);
    k_convmma< 64,  64, 1, 64, false, true , 64, 4,   0, false, false><<<gridT, 256, SM64>>>(h1, nullptr, w2h, w2l, b2, h2);
    k_convmma< 64,  64, 1, 32, false, true , 32, 4,   0, false, false><<<gridT, 256, SM32>>>(h2, nullptr, w3h, w3l, b3, h3);
    k_convmma< 32,  64, 1, 16, false, false,  2, 2,   0, false, false><<<gridT, 256, SM16>>>(h3, nullptr, w4h, w4l, b4, out);
}

// round 14
// speedup vs baseline: 1.0965x; 1.0270x over previous
#include <cuda_runtime.h>
#include <cuda_bf16.h>
#include <cstdint>

#define B_ 8
#define C_ 128
#define H_ 128
#define W_ 224
#define S_ 81
#define HW_ (H_*W_)

// ---------------- scratch (no allocations allowed) ----------------
__device__ float g_corr[B_*S_*HW_];      // 74.3 MB
__device__ float g_h1  [B_*64*HW_];      // 58.7 MB
__device__ float g_h2  [B_*64*HW_];      // 58.7 MB
__device__ float g_h3  [B_*32*HW_];      // 29.3 MB
// bf16 split weights, layout [shift s][oc][Cpad] (channel-major rows)
__device__ __nv_bfloat16 g_w1h[9*64*256];
__device__ __nv_bfloat16 g_w1l[9*64*256];
__device__ __nv_bfloat16 g_w2h[9*64*64];
__device__ __nv_bfloat16 g_w2l[9*64*64];
__device__ __nv_bfloat16 g_w3h[9*32*64];
__device__ __nv_bfloat16 g_w3l[9*32*64];
__device__ __nv_bfloat16 g_w4h[9*16*64];   // oc padded 2->16
__device__ __nv_bfloat16 g_w4l[9*16*64];

// ---------------- helpers ----------------
__device__ __forceinline__ uint32_t smem_u32(const void* p) {
    uint32_t a;
    asm("{ .reg .u64 t; cvta.to.shared.u64 t, %1; cvt.u32.u64 %0, t; }" : "=r"(a) : "l"(p));
    return a;
}
__device__ __forceinline__ void cpa4(void* smem_dst, const float* gsrc, bool ok) {
    uint32_t d = (uint32_t)__cvta_generic_to_shared(smem_dst);
    asm volatile("cp.async.ca.shared.global [%0], [%1], 4, %2;"
                 :: "r"(d), "l"(gsrc), "r"(ok ? 4 : 0));
}
__device__ __forceinline__ void cpa16(uint32_t smem_dst, const void* gsrc) {
    asm volatile("cp.async.cg.shared.global [%0], [%1], 16;"
                 :: "r"(smem_dst), "l"(gsrc));
}
__device__ __forceinline__ void cpa_commit() { asm volatile("cp.async.commit_group;" ::: "memory"); }
__device__ __forceinline__ void cpa_wait_all() { asm volatile("cp.async.wait_group 0;" ::: "memory"); }
__device__ __forceinline__ void cpa_wait1()   { asm volatile("cp.async.wait_group 1;" ::: "memory"); }

__device__ __forceinline__ uint32_t sw128(uint32_t b) { return b ^ ((b >> 3) & 0x70); }

__device__ __forceinline__ void ldsm4(uint32_t* r, uint32_t addr) {
    asm volatile("ldmatrix.sync.aligned.m8n8.x4.shared.b16 {%0,%1,%2,%3}, [%4];"
                 : "=r"(r[0]), "=r"(r[1]), "=r"(r[2]), "=r"(r[3]) : "r"(addr));
}
__device__ __forceinline__ void mma_bf16(float* c, const uint32_t* a, const uint32_t* b) {
    asm volatile("mma.sync.aligned.m16n8k16.row.col.f32.bf16.bf16.f32 "
                 "{%0,%1,%2,%3}, {%4,%5,%6,%7}, {%8,%9}, {%0,%1,%2,%3};"
                 : "+f"(c[0]), "+f"(c[1]), "+f"(c[2]), "+f"(c[3])
                 : "r"(a[0]), "r"(a[1]), "r"(a[2]), "r"(a[3]), "r"(b[0]), "r"(b[1]));
}
__device__ __forceinline__ uint32_t bf16x2(float hi, float lo) {
    uint32_t r;
    asm("cvt.rn.bf16x2.f32 %0, %1, %2;" : "=r"(r) : "f"(hi), "f"(lo));
    return r;
}

// ------- weight reorder + split: [oc][ci][3][3] -> [s][oc][Cpad], zero-pad c & oc ----
__global__ void k_reorder_split(const float* __restrict__ w, __nv_bfloat16* __restrict__ wh,
                                __nv_bfloat16* __restrict__ wl, int CIN, int COUT, int Cpad,
                                int COUTR) {
    int i = blockIdx.x * 256 + threadIdx.x;
    if (i >= 9 * COUT * Cpad) return;
    int c = i % Cpad;
    int t2 = i / Cpad;
    int oc = t2 % COUT, s = t2 / COUT;
    float v = (c < CIN && oc < COUTR) ? w[(oc * CIN + c) * 9 + s] : 0.0f;
    __nv_bfloat16 h = __float2bfloat16(v);
    wh[i] = h;
    wl[i] = __float2bfloat16(v - __bfloat162float(h));
}

// ---------------- correlation (R9 scalar version — proven 361us) ----------
__global__ void __launch_bounds__(256, 2) k_corr(const float* __restrict__ x1,
                                                 const float* __restrict__ x2) {
    __shared__ __align__(16) float x2s[2][4][16][40];
    const int tid = threadIdx.x;
    const int col = tid & 31, row = tid >> 5;
    const int w0 = blockIdx.x * 32, h0 = blockIdx.y * 8, b = blockIdx.z;

    float acc[81];
#pragma unroll
    for (int s = 0; s < 81; s++) acc[s] = 0.f;

    auto load_chunk = [&](int c0, int buf) {
        float* base = &x2s[buf][0][0][0];
        for (int idx = tid; idx < 4 * 16 * 40; idx += 256) {
            int c = idx / 640, r2 = idx % 640, rr = r2 / 40, cc = r2 % 40;
            int gh = h0 + rr - 4, gw = w0 + cc - 4;
            bool ok = (gh >= 0 && gh < H_ && gw >= 0 && gw < W_);
            const float* src = x2 + ((size_t)(b * C_ + c0 + c) * H_ + (ok ? gh : 0)) * W_ + (ok ? gw : 0);
            cpa4(base + idx, src, ok);
        }
    };

    load_chunk(0, 0);
    cpa_commit();

    int p = 0;
    for (int c0 = 0; c0 < C_; c0 += 4, p ^= 1) {
        cpa_wait_all();
        __syncthreads();
        if (c0 + 4 < C_) load_chunk(c0 + 4, p ^ 1);
        cpa_commit();

        float x1r[4];
#pragma unroll
        for (int c = 0; c < 4; c++)
            x1r[c] = x1[((b * C_ + c0 + c) * H_ + h0 + row) * W_ + w0 + col];
#pragma unroll
        for (int c = 0; c < 4; c++) {
            float v = x1r[c];
#pragma unroll
            for (int dy = 0; dy < 9; dy++)
#pragma unroll
                for (int dx = 0; dx < 9; dx++)
                    acc[dy * 9 + dx] += v * x2s[p][c][row + dy][col + dx];
        }
    }
#pragma unroll
    for (int s = 0; s < 81; s++)
        g_corr[((b * S_ + s) * H_ + h0 + row) * W_ + w0 + col] = acc[s] * (1.0f / 128.0f);
}

// ------- shift-decomposed mma.sync conv, NG-way warp tiling over N ---------------
// 8 warps = (8/NG) m-groups x NG n-groups. Each warp: NG m16-blocks x COUT/NG ocs.
// NG=2 balances ldsm redundancy (A 2x, B 4x -> 64 x4/CTA-kc vs 80 at NG=1).
// CHOFF: channel offset; ACCIN: acc from out; RAWOUT: raw partial write.
template<int CIN, int Cpad, int NCHUNK, int COUT, bool SPLIT, bool LEAKY, int NWRITE,
         int LASTKC, int CHOFF, bool ACCIN, bool RAWOUT, int NG>
__global__ void __launch_bounds__(256, 2) k_convmma(const float* __restrict__ in,
                                                    const float* __restrict__ in2,
                                                    const __nv_bfloat16* __restrict__ wh,
                                                    const __nv_bfloat16* __restrict__ wl,
                                                    const float* __restrict__ bias,
                                                    float* __restrict__ out) {
    constexpr int ASZ = 180 * 128;       // halo: 180 px rows x 128B (64ch bf16)
    constexpr int BSZ = COUT * 128;      // B tile: COUT rows x 128B
    constexpr int WM  = NG;              // m16-blocks per warp
    constexpr int NPW = (COUT / NG) / 16; // n16-pairs per warp (>=1)
    constexpr int NTW = 2 * NPW;          // n8-tiles per warp
    constexpr int T = NCHUNK * 9;

    extern __shared__ __align__(16) char smem_raw[];
    const uint32_t sb = smem_u32(smem_raw);
    const uint32_t Ah = sb, Al = sb + ASZ, Bb = sb + 2 * ASZ;
    const int tid = threadIdx.x, lane = tid & 31, wrp = tid >> 5;
    const int w0 = blockIdx.x * 16, h0 = blockIdx.y * 8, b = blockIdx.z;

    const int wm = wrp / NG, wn = wrp % NG;      // m-group, n-group
    const int nb = wn * (COUT / NG);             // oc base for this warp

    const int sub = lane >> 3, r8 = lane & 7;
    const int ak8 = (sub >> 1) << 3;
    const int bn_l = r8 + ((sub >> 1) << 3);
    const int bk8 = (sub & 1) << 3;

    // per-m-block A-row components
    int pr_[WM], pc_[WM];
#pragma unroll
    for (int mb = 0; mb < WM; mb++) {
        int am = wm * 16 * NG + mb * 16 + r8 + ((sub & 1) << 3);  // pixel 0..127
        pr_[mb] = am >> 4;
        pc_[mb] = am & 15;
    }

    // epilogue/acc-in addressing
    const int cb = (lane % 4) * 2;
    int m1_[WM];
#pragma unroll
    for (int mb = 0; mb < WM; mb++) m1_[mb] = wm * 16 * NG + mb * 16 + lane / 4;

    float acc[WM][NTW][4];
    if (ACCIN) {
#pragma unroll
        for (int mb = 0; mb < WM; mb++) {
            int m1 = m1_[mb], m2 = m1 + 8;
            int gh1 = h0 + (m1 >> 4), gw1 = w0 + (m1 & 15);
            int gh2 = h0 + (m2 >> 4), gw2 = w0 + (m2 & 15);
#pragma unroll
            for (int nt = 0; nt < NTW; nt++) {
                int n0 = nb + nt * 8 + cb;
                acc[mb][nt][0] = out[((size_t)(b * NWRITE + n0    ) * H_ + gh1) * W_ + gw1];
                acc[mb][nt][1] = out[((size_t)(b * NWRITE + n0 + 1) * H_ + gh1) * W_ + gw1];
                acc[mb][nt][2] = out[((size_t)(b * NWRITE + n0    ) * H_ + gh2) * W_ + gw2];
                acc[mb][nt][3] = out[((size_t)(b * NWRITE + n0 + 1) * H_ + gh2) * W_ + gw2];
            }
        }
    } else {
#pragma unroll
        for (int mb = 0; mb < WM; mb++)
#pragma unroll
            for (int nt = 0; nt < NTW; nt++)
#pragma unroll
                for (int j = 0; j < 4; j++) acc[mb][nt][j] = 0.f;
    }

    auto stage_halo = [&](int i) {
        constexpr int HITER = (32 * 180 + 255) / 256;   // 23
#pragma unroll
        for (int j = 0; j < HITER; j++) {
            int e = tid + j * 256;
            if (e < 32 * 180) {
                int c2 = e / 180, hp = e - c2 * 180;
                int hr = hp / 18, hc = hp - hr * 18;
                int gh = h0 + hr - 1, gw = w0 + hc - 1;
                bool okp = (gh >= 0 && gh < H_ && gw >= 0 && gw < W_);
                int c0 = CHOFF + i * 64 + c2 * 2;
                float v0 = 0.f, v1 = 0.f;
                if (okp) {
                    if (SPLIT) {
                        if (c0 < 128) {
                            v0 = in[((size_t)(b * 128 + c0    ) * H_ + gh) * W_ + gw];
                            v1 = in[((size_t)(b * 128 + c0 + 1) * H_ + gh) * W_ + gw];
                        } else {
                            if (c0     < 209) v0 = in2[((size_t)(b * 81 + (c0     - 128)) * H_ + gh) * W_ + gw];
                            if (c0 + 1 < 209) v1 = in2[((size_t)(b * 81 + (c0 + 1 - 128)) * H_ + gh) * W_ + gw];
                        }
                    } else {
                        if (c0     < CIN) v0 = in[((size_t)(b * CIN + c0    ) * H_ + gh) * W_ + gw];
                        if (c0 + 1 < CIN) v1 = in[((size_t)(b * CIN + c0 + 1) * H_ + gh) * W_ + gw];
                    }
                }
                uint32_t hpk = bf16x2(v1, v0);
                float l0 = v0 - __uint_as_float(hpk << 16);
                float l1 = v1 - __uint_as_float(hpk & 0xffff0000u);
                uint32_t lpk = bf16x2(l1, l0);
                uint32_t off = (uint32_t)hp * 128 + (((uint32_t)c2 * 4) ^ ((uint32_t)(hp & 7) << 4));
                *(uint32_t*)(smem_raw + off)       = hpk;
                *(uint32_t*)(smem_raw + ASZ + off) = lpk;
            }
        }
    };
    auto stage_B = [&](int t1, int buf) {
        int s = t1 % 9, ig = CHOFF / 64 + t1 / 9;
#pragma unroll
        for (int j = 0; j < (COUT * 16 + 255) / 256; j++) {
            int q = tid + j * 256;
            if (q < COUT * 16) {
                int split = q / (COUT * 8);
                int r = q - split * (COUT * 8);
                int oc = r >> 3, seg = r & 7;
                const __nv_bfloat16* src =
                    (split ? wl : wh) + (size_t)(s * COUT + oc) * Cpad + ig * 64 + seg * 8;
                cpa16(Bb + (uint32_t)(buf * 2 + split) * BSZ + sw128((uint32_t)(oc * 128 + seg * 16)), src);
            }
        }
        cpa_commit();
    };

    stage_B(0, 0);
    if (T > 1) stage_B(1, 1);
    int t = 0;
    for (int i = 0; i < NCHUNK; i++) {
        __syncthreads();
        stage_halo(i);
        const int kcmax = (i == NCHUNK - 1) ? LASTKC : 4;
#pragma unroll 1
        for (int s = 0; s < 9; s++) {
            if (t + 1 < T) cpa_wait1(); else cpa_wait_all();
            __syncthreads();
            if (t + 2 < T) stage_B(t + 2, (t + 2) % 3);
            const int buf = t % 3;

            const int ky = s / 3, kx = s - ky * 3;
            const uint32_t Bhc = Bb + (uint32_t)(buf * 2 + 0) * BSZ;
            const uint32_t Blc = Bb + (uint32_t)(buf * 2 + 1) * BSZ;
            uint32_t arow_[WM], axor_[WM];
#pragma unroll
            for (int mb = 0; mb < WM; mb++) {
                int hr = (pr_[mb] + ky) * 18 + (pc_[mb] + kx);
                arow_[mb] = (uint32_t)hr * 128;
                axor_[mb] = (uint32_t)(hr & 7) << 4;
            }
#pragma unroll
            for (int kc = 0; kc < 4; kc++) {
                if (kc < kcmax) {
                    uint32_t ahf[WM][4], alf[WM][4];
#pragma unroll
                    for (int mb = 0; mb < WM; mb++) {
                        uint32_t ka = ((uint32_t)((kc * 16 + ak8) * 2)) ^ axor_[mb];
                        ldsm4(ahf[mb], Ah + arow_[mb] + ka);
                        ldsm4(alf[mb], Al + arow_[mb] + ka);
                    }
                    uint32_t bhf[NPW][4], blf[NPW][4];
#pragma unroll
                    for (int pp = 0; pp < NPW; pp++) {
                        int bn = nb + pp * 16 + bn_l;
                        uint32_t boff = (uint32_t)bn * 128
                                      + (((uint32_t)((kc * 16 + bk8) * 2)) ^ ((uint32_t)(bn & 7) << 4));
                        ldsm4(bhf[pp], Bhc + boff);
                        ldsm4(blf[pp], Blc + boff);
                    }
#pragma unroll
                    for (int mb = 0; mb < WM; mb++)
#pragma unroll
                        for (int pp = 0; pp < NPW; pp++) {
                            mma_bf16(acc[mb][2 * pp],     ahf[mb], bhf[pp]);
                            mma_bf16(acc[mb][2 * pp + 1], ahf[mb], bhf[pp] + 2);
                        }
#pragma unroll
                    for (int mb = 0; mb < WM; mb++)
#pragma unroll
                        for (int pp = 0; pp < NPW; pp++) {
                            mma_bf16(acc[mb][2 * pp],     ahf[mb], blf[pp]);
                            mma_bf16(acc[mb][2 * pp + 1], ahf[mb], blf[pp] + 2);
                        }
#pragma unroll
                    for (int mb = 0; mb < WM; mb++)
#pragma unroll
                        for (int pp = 0; pp < NPW; pp++) {
                            mma_bf16(acc[mb][2 * pp],     alf[mb], bhf[pp]);
                            mma_bf16(acc[mb][2 * pp + 1], alf[mb], bhf[pp] + 2);
                        }
                }
            }
            t++;
        }
    }

#pragma unroll
    for (int mb = 0; mb < WM; mb++) {
        int m1 = m1_[mb], m2 = m1 + 8;
        int gh1 = h0 + (m1 >> 4), gw1 = w0 + (m1 & 15);
        int gh2 = h0 + (m2 >> 4), gw2 = w0 + (m2 & 15);
#pragma unroll
        for (int nt = 0; nt < NTW; nt++) {
            int n0 = nb + nt * 8 + cb;
            if (n0 < NWRITE) {
                float v00 = acc[mb][nt][0], v01 = acc[mb][nt][1];
                float v10 = acc[mb][nt][2], v11 = acc[mb][nt][3];
                if (!RAWOUT) {
                    float b0v = bias[n0], b1v = bias[n0 + 1];
                    v00 += b0v; v01 += b1v; v10 += b0v; v11 += b1v;
                    if (LEAKY) {
                        v00 = fmaxf(v00, 0.1f * v00); v01 = fmaxf(v01, 0.1f * v01);
                        v10 = fmaxf(v10, 0.1f * v10); v11 = fmaxf(v11, 0.1f * v11);
                    }
                }
                out[((size_t)(b * NWRITE + n0    ) * H_ + gh1) * W_ + gw1] = v00;
                out[((size_t)(b * NWRITE + n0 + 1) * H_ + gh1) * W_ + gw1] = v01;
                out[((size_t)(b * NWRITE + n0    ) * H_ + gh2) * W_ + gw2] = v10;
                out[((size_t)(b * NWRITE + n0 + 1) * H_ + gh2) * W_ + gw2] = v11;
            }
        }
    }
}

// ---------------- launch ----------------
extern "C" void kernel_launch(void* const* d_in, const int* in_sizes, int n_in,
                              void* d_out, int out_size) {
    (void)in_sizes; (void)n_in; (void)out_size;
    const float* x1 = (const float*)d_in[0];
    const float* x2 = (const float*)d_in[1];
    const float* w1 = (const float*)d_in[2];
    const float* b1 = (const float*)d_in[3];
    const float* w2 = (const float*)d_in[4];
    const float* b2 = (const float*)d_in[5];
    const float* w3 = (const float*)d_in[6];
    const float* b3 = (const float*)d_in[7];
    const float* w4 = (const float*)d_in[8];
    const float* b4 = (const float*)d_in[9];
    float* out = (float*)d_out;

    float *corr, *h1, *h2, *h3;
    __nv_bfloat16 *w1h, *w1l, *w2h, *w2l, *w3h, *w3l, *w4h, *w4l;
    cudaGetSymbolAddress((void**)&corr, g_corr);
    cudaGetSymbolAddress((void**)&h1,   g_h1);
    cudaGetSymbolAddress((void**)&h2,   g_h2);
    cudaGetSymbolAddress((void**)&h3,   g_h3);
    cudaGetSymbolAddress((void**)&w1h,  g_w1h);
    cudaGetSymbolAddress((void**)&w1l,  g_w1l);
    cudaGetSymbolAddress((void**)&w2h,  g_w2h);
    cudaGetSymbolAddress((void**)&w2l,  g_w2l);
    cudaGetSymbolAddress((void**)&w3h,  g_w3h);
    cudaGetSymbolAddress((void**)&w3l,  g_w3l);
    cudaGetSymbolAddress((void**)&w4h,  g_w4h);
    cudaGetSymbolAddress((void**)&w4l,  g_w4l);

    constexpr int SM64 = 2 * 180 * 128 + 6 * 64 * 128;   // 95232
    constexpr int SM32 = 2 * 180 * 128 + 6 * 32 * 128;   // 70656
    constexpr int SM16 = 2 * 180 * 128 + 6 * 16 * 128;   // 58368

    static cudaStream_t s2;
    static cudaEvent_t evFork, evJoin;
    static bool init_done = false;
    if (!init_done) {
        cudaStreamCreateWithFlags(&s2, cudaStreamNonBlocking);
        cudaEventCreateWithFlags(&evFork, cudaEventDisableTiming);
        cudaEventCreateWithFlags(&evJoin, cudaEventDisableTiming);
        cudaFuncSetAttribute(k_convmma<128, 256, 2, 64, false, false, 64, 4,   0, false, true , 2>, cudaFuncAttributeMaxDynamicSharedMemorySize, SM64);
        cudaFuncSetAttribute(k_convmma<209, 256, 2, 64, true , true , 64, 2, 128, true , false, 2>, cudaFuncAttributeMaxDynamicSharedMemorySize, SM64);
        cudaFuncSetAttribute(k_convmma< 64,  64, 1, 64, false, true , 64, 4,   0, false, false, 2>, cudaFuncAttributeMaxDynamicSharedMemorySize, SM64);
        cudaFuncSetAttribute(k_convmma< 64,  64, 1, 32, false, true , 32, 4,   0, false, false, 2>, cudaFuncAttributeMaxDynamicSharedMemorySize, SM32);
        cudaFuncSetAttribute(k_convmma< 32,  64, 1, 16, false, false,  2, 2,   0, false, false, 1>, cudaFuncAttributeMaxDynamicSharedMemorySize, SM16);
        init_done = true;
    }

    dim3 gridC(W_ / 32, H_ / 8, B_);   // (7, 16, 8)  corr
    dim3 gridT(W_ / 16, H_ / 8, B_);   // (14, 16, 8) mma convs

    // Fork: corr on s2 (neutral but harmless), overlap with reorders + conv1a.
    cudaEventRecord(evFork, 0);
    cudaStreamWaitEvent(s2, evFork, 0);
    k_corr<<<gridC, 256, 0, s2>>>(x1, x2);
    cudaEventRecord(evJoin, s2);

    k_reorder_split<<<(9 * 64 * 256 + 255) / 256, 256>>>(w1, w1h, w1l, 209, 64, 256, 64);
    k_reorder_split<<<(9 * 64 * 64  + 255) / 256, 256>>>(w2, w2h, w2l,  64, 64,  64, 64);
    k_reorder_split<<<(9 * 32 * 64  + 255) / 256, 256>>>(w3, w3h, w3l,  64, 32,  64, 32);
    k_reorder_split<<<(9 * 16 * 64  + 255) / 256, 256>>>(w4, w4h, w4l,  32, 16,  64,  2);

    // conv1a: x1 channels 0..127 -> raw partial sums into h1
    k_convmma<128, 256, 2, 64, false, false, 64, 4,   0, false, true , 2><<<gridT, 256, SM64>>>(x1, nullptr, w1h, w1l, b1, h1);

    cudaStreamWaitEvent(0, evJoin, 0);

    // conv1b: corr channels 128..208, acc-in from h1, bias + leaky
    k_convmma<209, 256, 2, 64, true , true , 64, 2, 128, true , false, 2><<<gridT, 256, SM64>>>(x1, corr, w1h, w1l, b1, h1);
    k_convmma< 64,  64, 1, 64, false, true , 64, 4,   0, false, false, 2><<<gridT, 256, SM64>>>(h1, nullptr, w2h, w2l, b2, h2);
    k_convmma< 64,  64, 1, 32, false, true , 32, 4,   0, false, false, 2><<<gridT, 256, SM32>>>(h2, nullptr, w3h, w3l, b3, h3);
    k_convmma< 32,  64, 1, 16, false, false,  2, 2,   0, false, false, 1><<<gridT, 256, SM16>>>(h3, nullptr, w4h, w4l, b4, out);
}

// round 15
// speedup vs baseline: 1.5092x; 1.3764x over previous
#include <cuda_runtime.h>
#include <cuda_fp16.h>
#include <cstdint>

#define B_ 8
#define C_ 128
#define H_ 128
#define W_ 224
#define S_ 81
#define HW_ (H_*W_)

// ---------------- scratch (no allocations allowed) ----------------
__device__ float g_corr[B_*S_*HW_];      // 74.3 MB
__device__ float g_h1  [B_*64*HW_];      // 58.7 MB
__device__ float g_h2  [B_*64*HW_];      // 58.7 MB
__device__ float g_h3  [B_*32*HW_];      // 29.3 MB
// fp16 weights, layout [shift s][oc][Cpad] (channel-major rows)
__device__ __half g_w1[9*64*256];
__device__ __half g_w2[9*64*64];
__device__ __half g_w3[9*32*64];
__device__ __half g_w4[9*16*64];         // oc padded 2->16

// ---------------- helpers ----------------
__device__ __forceinline__ uint32_t smem_u32(const void* p) {
    uint32_t a;
    asm("{ .reg .u64 t; cvta.to.shared.u64 t, %1; cvt.u32.u64 %0, t; }" : "=r"(a) : "l"(p));
    return a;
}
__device__ __forceinline__ void cpa4(void* smem_dst, const float* gsrc, bool ok) {
    uint32_t d = (uint32_t)__cvta_generic_to_shared(smem_dst);
    asm volatile("cp.async.ca.shared.global [%0], [%1], 4, %2;"
                 :: "r"(d), "l"(gsrc), "r"(ok ? 4 : 0));
}
__device__ __forceinline__ void cpa16(uint32_t smem_dst, const void* gsrc) {
    asm volatile("cp.async.cg.shared.global [%0], [%1], 16;"
                 :: "r"(smem_dst), "l"(gsrc));
}
__device__ __forceinline__ void cpa_commit() { asm volatile("cp.async.commit_group;" ::: "memory"); }
__device__ __forceinline__ void cpa_wait_all() { asm volatile("cp.async.wait_group 0;" ::: "memory"); }
__device__ __forceinline__ void cpa_wait1()   { asm volatile("cp.async.wait_group 1;" ::: "memory"); }

__device__ __forceinline__ uint32_t sw128(uint32_t b) { return b ^ ((b >> 3) & 0x70); }

__device__ __forceinline__ void ldsm4(uint32_t* r, uint32_t addr) {
    asm volatile("ldmatrix.sync.aligned.m8n8.x4.shared.b16 {%0,%1,%2,%3}, [%4];"
                 : "=r"(r[0]), "=r"(r[1]), "=r"(r[2]), "=r"(r[3]) : "r"(addr));
}
__device__ __forceinline__ void mma_f16(float* c, const uint32_t* a, const uint32_t* b) {
    asm volatile("mma.sync.aligned.m16n8k16.row.col.f32.f16.f16.f32 "
                 "{%0,%1,%2,%3}, {%4,%5,%6,%7}, {%8,%9}, {%0,%1,%2,%3};"
                 : "+f"(c[0]), "+f"(c[1]), "+f"(c[2]), "+f"(c[3])
                 : "r"(a[0]), "r"(a[1]), "r"(a[2]), "r"(a[3]), "r"(b[0]), "r"(b[1]));
}
__device__ __forceinline__ uint32_t f16x2(float hi, float lo) {
    uint32_t r;
    asm("cvt.rn.f16x2.f32 %0, %1, %2;" : "=r"(r) : "f"(hi), "f"(lo));
    return r;
}

// ------- weight reorder fp16: [oc][ci][3][3] -> [s][oc][Cpad], zero-pad c & oc ------
__global__ void k_reorder(const float* __restrict__ w, __half* __restrict__ wo,
                          int CIN, int COUT, int Cpad, int COUTR) {
    int i = blockIdx.x * 256 + threadIdx.x;
    if (i >= 9 * COUT * Cpad) return;
    int c = i % Cpad;
    int t2 = i / Cpad;
    int oc = t2 % COUT, s = t2 / COUT;
    float v = (c < CIN && oc < COUTR) ? w[(oc * CIN + c) * 9 + s] : 0.0f;
    wo[i] = __float2half(v);
}

// ---------------- correlation (R9 scalar version — proven 361us, fp32 exact) -------
__global__ void __launch_bounds__(256, 2) k_corr(const float* __restrict__ x1,
                                                 const float* __restrict__ x2) {
    __shared__ __align__(16) float x2s[2][4][16][40];
    const int tid = threadIdx.x;
    const int col = tid & 31, row = tid >> 5;
    const int w0 = blockIdx.x * 32, h0 = blockIdx.y * 8, b = blockIdx.z;

    float acc[81];
#pragma unroll
    for (int s = 0; s < 81; s++) acc[s] = 0.f;

    auto load_chunk = [&](int c0, int buf) {
        float* base = &x2s[buf][0][0][0];
        for (int idx = tid; idx < 4 * 16 * 40; idx += 256) {
            int c = idx / 640, r2 = idx % 640, rr = r2 / 40, cc = r2 % 40;
            int gh = h0 + rr - 4, gw = w0 + cc - 4;
            bool ok = (gh >= 0 && gh < H_ && gw >= 0 && gw < W_);
            const float* src = x2 + ((size_t)(b * C_ + c0 + c) * H_ + (ok ? gh : 0)) * W_ + (ok ? gw : 0);
            cpa4(base + idx, src, ok);
        }
    };

    load_chunk(0, 0);
    cpa_commit();

    int p = 0;
    for (int c0 = 0; c0 < C_; c0 += 4, p ^= 1) {
        cpa_wait_all();
        __syncthreads();
        if (c0 + 4 < C_) load_chunk(c0 + 4, p ^ 1);
        cpa_commit();

        float x1r[4];
#pragma unroll
        for (int c = 0; c < 4; c++)
            x1r[c] = x1[((b * C_ + c0 + c) * H_ + h0 + row) * W_ + w0 + col];
#pragma unroll
        for (int c = 0; c < 4; c++) {
            float v = x1r[c];
#pragma unroll
            for (int dy = 0; dy < 9; dy++)
#pragma unroll
                for (int dx = 0; dx < 9; dx++)
                    acc[dy * 9 + dx] += v * x2s[p][c][row + dy][col + dx];
        }
    }
#pragma unroll
    for (int s = 0; s < 81; s++)
        g_corr[((b * S_ + s) * H_ + h0 + row) * W_ + w0 + col] = acc[s] * (1.0f / 128.0f);
}

// ------- shift-decomposed mma.sync conv, fp16 single-pass, NG=2 warp tiling --------
// 8 warps = (8/NG) m-groups x NG n-groups; each warp NG m16-blocks x COUT/NG ocs.
// Halo 10x18 px x 64ch fp16 (SW128, single buffer) staged per chunk; ldmatrix reads
// A directly with per-shift row offsets. B [s][oc][c] fp16 triple-buffered cp.async.
// D = A*B in one pass (f32 acc). CHOFF/ACCIN/RAWOUT as before.
template<int CIN, int Cpad, int NCHUNK, int COUT, bool SPLIT, bool LEAKY, int NWRITE,
         int LASTKC, int CHOFF, bool ACCIN, bool RAWOUT, int NG>
__global__ void __launch_bounds__(256, 2) k_convmma(const float* __restrict__ in,
                                                    const float* __restrict__ in2,
                                                    const __half* __restrict__ wq,
                                                    const float* __restrict__ bias,
                                                    float* __restrict__ out) {
    constexpr int ASZ = 180 * 128;       // halo: 180 px rows x 128B (64ch fp16)
    constexpr int BSZ = COUT * 128;      // B tile: COUT rows x 128B
    constexpr int WM  = NG;              // m16-blocks per warp
    constexpr int NPW = (COUT / NG) / 16; // n16-pairs per warp
    constexpr int NTW = 2 * NPW;          // n8-tiles per warp
    constexpr int T = NCHUNK * 9;

    extern __shared__ __align__(16) char smem_raw[];
    const uint32_t sb = smem_u32(smem_raw);
    const uint32_t Ab = sb, Bb = sb + ASZ;
    const int tid = threadIdx.x, lane = tid & 31, wrp = tid >> 5;
    const int w0 = blockIdx.x * 16, h0 = blockIdx.y * 8, b = blockIdx.z;

    const int wm = wrp / NG, wn = wrp % NG;
    const int nb = wn * (COUT / NG);

    const int sub = lane >> 3, r8 = lane & 7;
    const int ak8 = (sub >> 1) << 3;
    const int bn_l = r8 + ((sub >> 1) << 3);
    const int bk8 = (sub & 1) << 3;

    int pr_[WM], pc_[WM];
#pragma unroll
    for (int mb = 0; mb < WM; mb++) {
        int am = wm * 16 * NG + mb * 16 + r8 + ((sub & 1) << 3);
        pr_[mb] = am >> 4;
        pc_[mb] = am & 15;
    }

    const int cb = (lane % 4) * 2;
    int m1_[WM];
#pragma unroll
    for (int mb = 0; mb < WM; mb++) m1_[mb] = wm * 16 * NG + mb * 16 + lane / 4;

    float acc[WM][NTW][4];
    if (ACCIN) {
#pragma unroll
        for (int mb = 0; mb < WM; mb++) {
            int m1 = m1_[mb], m2 = m1 + 8;
            int gh1 = h0 + (m1 >> 4), gw1 = w0 + (m1 & 15);
            int gh2 = h0 + (m2 >> 4), gw2 = w0 + (m2 & 15);
#pragma unroll
            for (int nt = 0; nt < NTW; nt++) {
                int n0 = nb + nt * 8 + cb;
                acc[mb][nt][0] = out[((size_t)(b * NWRITE + n0    ) * H_ + gh1) * W_ + gw1];
                acc[mb][nt][1] = out[((size_t)(b * NWRITE + n0 + 1) * H_ + gh1) * W_ + gw1];
                acc[mb][nt][2] = out[((size_t)(b * NWRITE + n0    ) * H_ + gh2) * W_ + gw2];
                acc[mb][nt][3] = out[((size_t)(b * NWRITE + n0 + 1) * H_ + gh2) * W_ + gw2];
            }
        }
    } else {
#pragma unroll
        for (int mb = 0; mb < WM; mb++)
#pragma unroll
            for (int nt = 0; nt < NTW; nt++)
#pragma unroll
                for (int j = 0; j < 4; j++) acc[mb][nt][j] = 0.f;
    }

    auto stage_halo = [&](int i) {
        constexpr int HITER = (32 * 180 + 255) / 256;   // 23
#pragma unroll
        for (int j = 0; j < HITER; j++) {
            int e = tid + j * 256;
            if (e < 32 * 180) {
                int c2 = e / 180, hp = e - c2 * 180;
                int hr = hp / 18, hc = hp - hr * 18;
                int gh = h0 + hr - 1, gw = w0 + hc - 1;
                bool okp = (gh >= 0 && gh < H_ && gw >= 0 && gw < W_);
                int c0 = CHOFF + i * 64 + c2 * 2;
                float v0 = 0.f, v1 = 0.f;
                if (okp) {
                    if (SPLIT) {
                        if (c0 < 128) {
                            v0 = in[((size_t)(b * 128 + c0    ) * H_ + gh) * W_ + gw];
                            v1 = in[((size_t)(b * 128 + c0 + 1) * H_ + gh) * W_ + gw];
                        } else {
                            if (c0     < 209) v0 = in2[((size_t)(b * 81 + (c0     - 128)) * H_ + gh) * W_ + gw];
                            if (c0 + 1 < 209) v1 = in2[((size_t)(b * 81 + (c0 + 1 - 128)) * H_ + gh) * W_ + gw];
                        }
                    } else {
                        if (c0     < CIN) v0 = in[((size_t)(b * CIN + c0    ) * H_ + gh) * W_ + gw];
                        if (c0 + 1 < CIN) v1 = in[((size_t)(b * CIN + c0 + 1) * H_ + gh) * W_ + gw];
                    }
                }
                uint32_t pk = f16x2(v1, v0);
                uint32_t off = (uint32_t)hp * 128 + (((uint32_t)c2 * 4) ^ ((uint32_t)(hp & 7) << 4));
                *(uint32_t*)(smem_raw + off) = pk;
            }
        }
    };
    auto stage_B = [&](int t1, int buf) {
        int s = t1 % 9, ig = CHOFF / 64 + t1 / 9;
#pragma unroll
        for (int j = 0; j < (COUT * 8 + 255) / 256; j++) {
            int q = tid + j * 256;
            if (q < COUT * 8) {
                int oc = q >> 3, seg = q & 7;
                const __half* src = wq + (size_t)(s * COUT + oc) * Cpad + ig * 64 + seg * 8;
                cpa16(Bb + (uint32_t)buf * BSZ + sw128((uint32_t)(oc * 128 + seg * 16)), src);
            }
        }
        cpa_commit();
    };

    stage_B(0, 0);
    if (T > 1) stage_B(1, 1);
    int t = 0;
    for (int i = 0; i < NCHUNK; i++) {
        __syncthreads();
        stage_halo(i);
        const int kcmax = (i == NCHUNK - 1) ? LASTKC : 4;
#pragma unroll 1
        for (int s = 0; s < 9; s++) {
            if (t + 1 < T) cpa_wait1(); else cpa_wait_all();
            __syncthreads();
            if (t + 2 < T) stage_B(t + 2, (t + 2) % 3);
            const int buf = t % 3;

            const int ky = s / 3, kx = s - ky * 3;
            const uint32_t Bc = Bb + (uint32_t)buf * BSZ;
            uint32_t arow_[WM], axor_[WM];
#pragma unroll
            for (int mb = 0; mb < WM; mb++) {
                int hr = (pr_[mb] + ky) * 18 + (pc_[mb] + kx);
                arow_[mb] = (uint32_t)hr * 128;
                axor_[mb] = (uint32_t)(hr & 7) << 4;
            }
#pragma unroll
            for (int kc = 0; kc < 4; kc++) {
                if (kc < kcmax) {
                    uint32_t af[WM][4];
#pragma unroll
                    for (int mb = 0; mb < WM; mb++) {
                        uint32_t ka = ((uint32_t)((kc * 16 + ak8) * 2)) ^ axor_[mb];
                        ldsm4(af[mb], Ab + arow_[mb] + ka);
                    }
                    uint32_t bf[NPW][4];
#pragma unroll
                    for (int pp = 0; pp < NPW; pp++) {
                        int bn = nb + pp * 16 + bn_l;
                        uint32_t boff = (uint32_t)bn * 128
                                      + (((uint32_t)((kc * 16 + bk8) * 2)) ^ ((uint32_t)(bn & 7) << 4));
                        ldsm4(bf[pp], Bc + boff);
                    }
#pragma unroll
                    for (int mb = 0; mb < WM; mb++)
#pragma unroll
                        for (int pp = 0; pp < NPW; pp++) {
                            mma_f16(acc[mb][2 * pp],     af[mb], bf[pp]);
                            mma_f16(acc[mb][2 * pp + 1], af[mb], bf[pp] + 2);
                        }
                }
            }
            t++;
        }
    }

#pragma unroll
    for (int mb = 0; mb < WM; mb++) {
        int m1 = m1_[mb], m2 = m1 + 8;
        int gh1 = h0 + (m1 >> 4), gw1 = w0 + (m1 & 15);
        int gh2 = h0 + (m2 >> 4), gw2 = w0 + (m2 & 15);
#pragma unroll
        for (int nt = 0; nt < NTW; nt++) {
            int n0 = nb + nt * 8 + cb;
            if (n0 < NWRITE) {
                float v00 = acc[mb][nt][0], v01 = acc[mb][nt][1];
                float v10 = acc[mb][nt][2], v11 = acc[mb][nt][3];
                if (!RAWOUT) {
                    float b0v = bias[n0], b1v = bias[n0 + 1];
                    v00 += b0v; v01 += b1v; v10 += b0v; v11 += b1v;
                    if (LEAKY) {
                        v00 = fmaxf(v00, 0.1f * v00); v01 = fmaxf(v01, 0.1f * v01);
                        v10 = fmaxf(v10, 0.1f * v10); v11 = fmaxf(v11, 0.1f * v11);
                    }
                }
                out[((size_t)(b * NWRITE + n0    ) * H_ + gh1) * W_ + gw1] = v00;
                out[((size_t)(b * NWRITE + n0 + 1) * H_ + gh1) * W_ + gw1] = v01;
                out[((size_t)(b * NWRITE + n0    ) * H_ + gh2) * W_ + gw2] = v10;
                out[((size_t)(b * NWRITE + n0 + 1) * H_ + gh2) * W_ + gw2] = v11;
            }
        }
    }
}

// ---------------- launch ----------------
extern "C" void kernel_launch(void* const* d_in, const int* in_sizes, int n_in,
                              void* d_out, int out_size) {
    (void)in_sizes; (void)n_in; (void)out_size;
    const float* x1 = (const float*)d_in[0];
    const float* x2 = (const float*)d_in[1];
    const float* w1 = (const float*)d_in[2];
    const float* b1 = (const float*)d_in[3];
    const float* w2 = (const float*)d_in[4];
    const float* b2 = (const float*)d_in[5];
    const float* w3 = (const float*)d_in[6];
    const float* b3 = (const float*)d_in[7];
    const float* w4 = (const float*)d_in[8];
    const float* b4 = (const float*)d_in[9];
    float* out = (float*)d_out;

    float *corr, *h1, *h2, *h3;
    __half *w1q, *w2q, *w3q, *w4q;
    cudaGetSymbolAddress((void**)&corr, g_corr);
    cudaGetSymbolAddress((void**)&h1,   g_h1);
    cudaGetSymbolAddress((void**)&h2,   g_h2);
    cudaGetSymbolAddress((void**)&h3,   g_h3);
    cudaGetSymbolAddress((void**)&w1q,  g_w1);
    cudaGetSymbolAddress((void**)&w2q,  g_w2);
    cudaGetSymbolAddress((void**)&w3q,  g_w3);
    cudaGetSymbolAddress((void**)&w4q,  g_w4);

    // smem: fp16 halo (23040) + B triple buffer (3 x BSZ)
    constexpr int SM64 = 180 * 128 + 3 * 64 * 128;   // 47616
    constexpr int SM32 = 180 * 128 + 3 * 32 * 128;   // 35328
    constexpr int SM16 = 180 * 128 + 3 * 16 * 128;   // 29184

    static cudaStream_t s2;
    static cudaEvent_t evFork, evJoin;
    static bool init_done = false;
    if (!init_done) {
        cudaStreamCreateWithFlags(&s2, cudaStreamNonBlocking);
        cudaEventCreateWithFlags(&evFork, cudaEventDisableTiming);
        cudaEventCreateWithFlags(&evJoin, cudaEventDisableTiming);
        cudaFuncSetAttribute(k_convmma<128, 256, 2, 64, false, false, 64, 4,   0, false, true , 2>, cudaFuncAttributeMaxDynamicSharedMemorySize, SM64);
        cudaFuncSetAttribute(k_convmma<209, 256, 2, 64, true , true , 64, 2, 128, true , false, 2>, cudaFuncAttributeMaxDynamicSharedMemorySize, SM64);
        cudaFuncSetAttribute(k_convmma< 64,  64, 1, 64, false, true , 64, 4,   0, false, false, 2>, cudaFuncAttributeMaxDynamicSharedMemorySize, SM64);
        cudaFuncSetAttribute(k_convmma< 64,  64, 1, 32, false, true , 32, 4,   0, false, false, 2>, cudaFuncAttributeMaxDynamicSharedMemorySize, SM32);
        cudaFuncSetAttribute(k_convmma< 32,  64, 1, 16, false, false,  2, 2,   0, false, false, 1>, cudaFuncAttributeMaxDynamicSharedMemorySize, SM16);
        init_done = true;
    }

    dim3 gridC(W_ / 32, H_ / 8, B_);   // (7, 16, 8)  corr
    dim3 gridT(W_ / 16, H_ / 8, B_);   // (14, 16, 8) mma convs

    // Fork: corr on s2, overlap with reorders + conv1a.
    cudaEventRecord(evFork, 0);
    cudaStreamWaitEvent(s2, evFork, 0);
    k_corr<<<gridC, 256, 0, s2>>>(x1, x2);
    cudaEventRecord(evJoin, s2);

    k_reorder<<<(9 * 64 * 256 + 255) / 256, 256>>>(w1, w1q, 209, 64, 256, 64);
    k_reorder<<<(9 * 64 * 64  + 255) / 256, 256>>>(w2, w2q,  64, 64,  64, 64);
    k_reorder<<<(9 * 32 * 64  + 255) / 256, 256>>>(w3, w3q,  64, 32,  64, 32);
    k_reorder<<<(9 * 16 * 64  + 255) / 256, 256>>>(w4, w4q,  32, 16,  64,  2);

    // conv1a: x1 channels 0..127 -> raw partial sums into h1
    k_convmma<128, 256, 2, 64, false, false, 64, 4,   0, false, true , 2><<<gridT, 256, SM64>>>(x1, nullptr, w1q, b1, h1);

    cudaStreamWaitEvent(0, evJoin, 0);

    // conv1b: corr channels 128..208, acc-in from h1, bias + leaky
    k_convmma<209, 256, 2, 64, true , true , 64, 2, 128, true , false, 2><<<gridT, 256, SM64>>>(x1, corr, w1q, b1, h1);
    k_convmma< 64,  64, 1, 64, false, true , 64, 4,   0, false, false, 2><<<gridT, 256, SM64>>>(h1, nullptr, w2q, b2, h2);
    k_convmma< 64,  64, 1, 32, false, true , 32, 4,   0, false, false, 2><<<gridT, 256, SM32>>>(h2, nullptr, w3q, b3, h3);
    k_convmma< 32,  64, 1, 16, false, false,  2, 2,   0, false, false, 1><<<gridT, 256, SM16>>>(h3, nullptr, w4q, b4, out);
}